// round 5
// baseline (speedup 1.0000x reference)
#include <cuda_runtime.h>
#include <math.h>

#define N_NODES 20000
#define N_EDGES 320000
#define ET (N_EDGES + N_NODES)   // edges + self loops = 340000
#define HID 128
#define LRELU_SLOPE 0.2f
#define BN_EPS 1e-5f

// ---------------- scratch (device globals; no allocation allowed) ----------------
__device__ float g_xl[N_NODES * 512];   // per-layer x@W
__device__ float g_h [N_NODES * 512];   // per-layer output (ping)
__device__ float g_h2[N_NODES * 128];   // layer-2 output
__device__ float g_z [N_NODES * 128];   // head hidden
__device__ float g_s[N_NODES * 4], g_d[N_NODES * 4];
__device__ float g_emax[N_NODES * 4], g_denom[N_NODES * 4];
__device__ float g_w[ET * 4];           // per-edge e -> unnormalized alpha
__device__ int g_src[ET], g_dst[ET];
__device__ int g_deg[N_NODES], g_off[N_NODES + 1], g_fill[N_NODES];
__device__ int g_csr_src[ET], g_csr_eid[ET];
__device__ int g_is64;                  // edge_index dtype flag (1 = int64)

// ---------------- small utility kernels ----------------
__global__ void detect_dtype_kernel(const int* __restrict__ ei32) {
    // int64 little-endian values in [0, N_NODES) have zero high words at all
    // odd 32-bit indices; int32 random node ids essentially never do (8x).
    if (threadIdx.x == 0 && blockIdx.x == 0) {
        int allz = 1;
        #pragma unroll
        for (int j = 0; j < 8; j++)
            if (ei32[2 * j + 1] != 0) allz = 0;
        g_is64 = allz;
    }
}

__global__ void zero_int2_kernel(int* a, int* b, int n) {
    int i = blockIdx.x * blockDim.x + threadIdx.x;
    if (i < n) { a[i] = 0; b[i] = 0; }
}

__global__ void init_softmax_kernel(float* emax, float* denom, int n) {
    int i = blockIdx.x * blockDim.x + threadIdx.x;
    if (i < n) { emax[i] = -3.0e38f; denom[i] = 0.f; }
}

__global__ void prep_edges_kernel(const int* __restrict__ ei32,
                                  int* __restrict__ src, int* __restrict__ dst,
                                  int* __restrict__ deg) {
    int i = blockIdx.x * blockDim.x + threadIdx.x;
    if (i >= ET) return;
    int u, v;
    if (i < N_EDGES) {
        if (g_is64) {
            u = ei32[2 * i];                     // low word of int64
            v = ei32[2 * (N_EDGES + i)];
        } else {
            u = ei32[i];
            v = ei32[N_EDGES + i];
        }
    } else {
        u = v = i - N_EDGES;                     // self loops
    }
    // defensive clamp (protects against any residual decode mismatch)
    u = min(max(u, 0), N_NODES - 1);
    v = min(max(v, 0), N_NODES - 1);
    src[i] = u; dst[i] = v;
    atomicAdd(&deg[v], 1);
}

// single-block exclusive scan of degrees -> offsets
__global__ void scan_kernel(const int* __restrict__ deg, int* __restrict__ off, int n) {
    __shared__ int partial[1024];
    int t = threadIdx.x;
    const int chunk = (n + 1023) / 1024;
    int start = t * chunk;
    int s = 0;
    for (int i = 0; i < chunk; i++) { int idx = start + i; if (idx < n) s += deg[idx]; }
    partial[t] = s;
    __syncthreads();
    for (int o = 1; o < 1024; o <<= 1) {
        int v = (t >= o) ? partial[t - o] : 0;
        __syncthreads();
        partial[t] += v;
        __syncthreads();
    }
    int run = (t == 0) ? 0 : partial[t - 1];
    for (int i = 0; i < chunk; i++) {
        int idx = start + i;
        if (idx < n) { off[idx] = run; run += deg[idx]; }
    }
    if (t == 1023) off[n] = partial[1023];
}

__global__ void fill_csr_kernel(const int* __restrict__ src, const int* __restrict__ dst,
                                const int* __restrict__ off, int* __restrict__ fill,
                                int* __restrict__ csr_src, int* __restrict__ csr_eid) {
    int i = blockIdx.x * blockDim.x + threadIdx.x;
    if (i >= ET) return;
    int v = dst[i];
    int pos = off[v] + atomicAdd(&fill[v], 1);
    csr_src[pos] = src[i];
    csr_eid[pos] = i;
}

// ---------------- fp32 SGEMM (generic; EPI=1 -> bias+relu) ----------------
template <int BM, int BN, int BK, int TM, int TN, int EPI>
__global__ void sgemm_kernel(const float* __restrict__ A, const float* __restrict__ B,
                             const float* __restrict__ bias, float* __restrict__ C,
                             int M, int N, int K) {
    constexpr int THREADS = (BM / TM) * (BN / TN);
    __shared__ float As[BK][BM + 4];
    __shared__ float Bs[BK][BN];
    const int tid = threadIdx.x;
    const int tx = tid % (BN / TN);
    const int ty = tid / (BN / TN);
    const int rowBase = blockIdx.y * BM;
    const int colBase = blockIdx.x * BN;
    float acc[TM][TN] = {};
    for (int k0 = 0; k0 < K; k0 += BK) {
        #pragma unroll
        for (int i = tid; i < BM * BK; i += THREADS) {
            int m = i / BK, kk = i % BK;
            int gr = rowBase + m, gk = k0 + kk;
            As[kk][m] = (gr < M && gk < K) ? A[(size_t)gr * K + gk] : 0.f;
        }
        #pragma unroll
        for (int i = tid; i < BK * BN; i += THREADS) {
            int kk = i / BN, nn = i % BN;
            int gk = k0 + kk, gc = colBase + nn;
            Bs[kk][nn] = (gk < K && gc < N) ? B[(size_t)gk * N + gc] : 0.f;
        }
        __syncthreads();
        #pragma unroll
        for (int kk = 0; kk < BK; kk++) {
            float a[TM], bb[TN];
            #pragma unroll
            for (int i = 0; i < TM; i++) a[i] = As[kk][ty * TM + i];
            #pragma unroll
            for (int j = 0; j < TN; j++) bb[j] = Bs[kk][tx * TN + j];
            #pragma unroll
            for (int i = 0; i < TM; i++)
                #pragma unroll
                for (int j = 0; j < TN; j++) acc[i][j] += a[i] * bb[j];
        }
        __syncthreads();
    }
    #pragma unroll
    for (int i = 0; i < TM; i++) {
        int r = rowBase + ty * TM + i;
        if (r >= M) continue;
        #pragma unroll
        for (int j = 0; j < TN; j++) {
            int c = colBase + tx * TN + j;
            if (c >= N) continue;
            float v = acc[i][j];
            if (EPI == 1) { v += bias[c]; v = v > 0.f ? v : 0.f; }
            C[(size_t)r * N + c] = v;
        }
    }
}

// ---------------- per-node attention score terms s, d ----------------
__global__ void sd_kernel(const float* __restrict__ xl, const float* __restrict__ a_src,
                          const float* __restrict__ a_dst, float* __restrict__ s,
                          float* __restrict__ d, int H) {
    int n = blockIdx.x;
    int w = threadIdx.x >> 5, l = threadIdx.x & 31;
    if (w >= H) return;
    const float* row = xl + (size_t)n * H * 128 + w * 128;
    float ps = 0.f, pd = 0.f;
    #pragma unroll
    for (int k = 0; k < 4; k++) {
        int c = l + 32 * k;
        float v = row[c];
        ps += v * a_src[w * 128 + c];
        pd += v * a_dst[w * 128 + c];
    }
    #pragma unroll
    for (int o = 16; o; o >>= 1) {
        ps += __shfl_down_sync(0xffffffffu, ps, o);
        pd += __shfl_down_sync(0xffffffffu, pd, o);
    }
    if (l == 0) { s[n * H + w] = ps; d[n * H + w] = pd; }
}

__device__ __forceinline__ void atomicMaxF(float* addr, float val) {
    int old = __float_as_int(*addr);
    while (__int_as_float(old) < val) {
        int assumed = old;
        old = atomicCAS((int*)addr, assumed, __float_as_int(val));
        if (old == assumed) break;
    }
}

__global__ void edge_max_kernel(const int* __restrict__ src, const int* __restrict__ dst,
                                const float* __restrict__ s, const float* __restrict__ d,
                                float* __restrict__ w, float* __restrict__ emax, int H) {
    int i = blockIdx.x * blockDim.x + threadIdx.x;
    if (i >= ET) return;
    int u = src[i], v = dst[i];
    for (int h = 0; h < H; h++) {
        float e = s[u * H + h] + d[v * H + h];
        e = e > 0.f ? e : LRELU_SLOPE * e;
        w[i * H + h] = e;
        atomicMaxF(&emax[v * H + h], e);
    }
}

__global__ void edge_exp_kernel(const int* __restrict__ dst, float* __restrict__ w,
                                const float* __restrict__ emax, float* __restrict__ denom,
                                int H) {
    int i = blockIdx.x * blockDim.x + threadIdx.x;
    if (i >= ET) return;
    int v = dst[i];
    for (int h = 0; h < H; h++) {
        float x = expf(w[i * H + h] - emax[v * H + h]);
        w[i * H + h] = x;
        atomicAdd(&denom[v * H + h], x);
    }
}

// ---------------- per-node weighted aggregation + bias + BN + ELU ----------------
template <int H>
__global__ void aggregate_kernel(const float* __restrict__ xl, const int* __restrict__ csr_src,
                                 const int* __restrict__ csr_eid, const int* __restrict__ off,
                                 const float* __restrict__ w, const float* __restrict__ denom,
                                 const float* __restrict__ bias, const float* __restrict__ bg,
                                 const float* __restrict__ bbe, const float* __restrict__ bm,
                                 const float* __restrict__ bv, float* __restrict__ out) {
    int n = blockIdx.x;
    int t = threadIdx.x;  // 128 threads
    float acc[H];
    #pragma unroll
    for (int h = 0; h < H; h++) acc[h] = 0.f;
    int s0 = off[n], s1 = off[n + 1];
    __shared__ int sh_src[32];
    __shared__ float sh_w[32][H];
    for (int base = s0; base < s1; base += 32) {
        int cnt = min(32, s1 - base);
        if (t < cnt) sh_src[t] = csr_src[base + t];
        if (t < cnt * H) {
            int j = t / H, h = t % H;
            sh_w[j][h] = w[csr_eid[base + j] * H + h];
        }
        __syncthreads();
        for (int j = 0; j < cnt; j++) {
            const float* row = xl + (size_t)sh_src[j] * (H * 128);
            #pragma unroll
            for (int h = 0; h < H; h++) acc[h] += sh_w[j][h] * row[h * 128 + t];
        }
        __syncthreads();
    }
    #pragma unroll
    for (int h = 0; h < H; h++) {
        int c = h * 128 + t;
        float val = acc[h] / (denom[n * H + h] + 1e-16f) + bias[c];
        float sc = bg[c] * rsqrtf(bv[c] + BN_EPS);
        val = (val - bm[c]) * sc + bbe[c];
        out[(size_t)n * (H * 128) + c] = val > 0.f ? val : expm1f(val);
    }
}

// ---------------- head layer 2: [N,128] @ [128,9] + bias ----------------
__global__ void head2_kernel(const float* __restrict__ z, const float* __restrict__ hw2,
                             const float* __restrict__ hb2, float* __restrict__ out) {
    int warp = (blockIdx.x * blockDim.x + threadIdx.x) >> 5;
    int lane = threadIdx.x & 31;
    if (warp >= N_NODES) return;
    const float* row = z + (size_t)warp * 128;
    float zv[4];
    #pragma unroll
    for (int i = 0; i < 4; i++) zv[i] = row[lane + 32 * i];
    for (int j = 0; j < 9; j++) {
        float p = 0.f;
        #pragma unroll
        for (int i = 0; i < 4; i++) p += zv[i] * hw2[(lane + 32 * i) * 9 + j];
        #pragma unroll
        for (int o = 16; o; o >>= 1) p += __shfl_down_sync(0xffffffffu, p, o);
        if (lane == 0) out[warp * 9 + j] = p + hb2[j];
    }
}

// ---------------- driver ----------------
static void run_gemm(const float* A, const float* B, const float* bias, float* C,
                     int M, int N, int K, int epi) {
    dim3 grid((N + 63) / 64, (M + 127) / 128);
    if (epi)
        sgemm_kernel<128, 64, 16, 8, 4, 1><<<grid, 256>>>(A, B, bias, C, M, N, K);
    else
        sgemm_kernel<128, 64, 16, 8, 4, 0><<<grid, 256>>>(A, B, bias, C, M, N, K);
}

extern "C" void kernel_launch(void* const* d_in, const int* in_sizes, int n_in,
                              void* d_out, int out_size) {
    const float* x = (const float*)d_in[0];
    const int* ei32 = (const int*)d_in[1];   // int32 OR int64 (detected on device)

    // Disambiguate input ordering: signature order has W1 (262144 elems) at idx 6,
    // dict order has g0 (512 elems) there.
    bool sig_order = (in_sizes[6] > 100000);
    const float *W[3], *a_src[3], *a_dst[3], *bb[3], *bg[3], *bbe[3], *bm[3], *bv[3];
    if (sig_order) {
        const int wi[3] = {2, 6, 10};
        const int gi[3] = {14, 18, 22};
        for (int i = 0; i < 3; i++) {
            W[i]     = (const float*)d_in[wi[i] + 0];
            a_src[i] = (const float*)d_in[wi[i] + 1];
            a_dst[i] = (const float*)d_in[wi[i] + 2];
            bb[i]    = (const float*)d_in[wi[i] + 3];
            bg[i]    = (const float*)d_in[gi[i] + 0];
            bbe[i]   = (const float*)d_in[gi[i] + 1];
            bm[i]    = (const float*)d_in[gi[i] + 2];
            bv[i]    = (const float*)d_in[gi[i] + 3];
        }
    } else {
        const int base[3] = {2, 10, 18};
        for (int i = 0; i < 3; i++) {
            W[i]     = (const float*)d_in[base[i] + 0];
            a_src[i] = (const float*)d_in[base[i] + 1];
            a_dst[i] = (const float*)d_in[base[i] + 2];
            bb[i]    = (const float*)d_in[base[i] + 3];
            bg[i]    = (const float*)d_in[base[i] + 4];
            bbe[i]   = (const float*)d_in[base[i] + 5];
            bm[i]    = (const float*)d_in[base[i] + 6];
            bv[i]    = (const float*)d_in[base[i] + 7];
        }
    }
    const float* hw1 = (const float*)d_in[26];
    const float* hb1 = (const float*)d_in[27];
    const float* hw2 = (const float*)d_in[28];
    const float* hb2 = (const float*)d_in[29];
    float* out = (float*)d_out;

    // scratch addresses
    float *xl, *hbuf, *h2, *z, *sS, *sD, *emax, *denom, *wbuf;
    int *src, *dst, *deg, *off, *fill, *csr_src, *csr_eid;
    cudaGetSymbolAddress((void**)&xl, g_xl);
    cudaGetSymbolAddress((void**)&hbuf, g_h);
    cudaGetSymbolAddress((void**)&h2, g_h2);
    cudaGetSymbolAddress((void**)&z, g_z);
    cudaGetSymbolAddress((void**)&sS, g_s);
    cudaGetSymbolAddress((void**)&sD, g_d);
    cudaGetSymbolAddress((void**)&emax, g_emax);
    cudaGetSymbolAddress((void**)&denom, g_denom);
    cudaGetSymbolAddress((void**)&wbuf, g_w);
    cudaGetSymbolAddress((void**)&src, g_src);
    cudaGetSymbolAddress((void**)&dst, g_dst);
    cudaGetSymbolAddress((void**)&deg, g_deg);
    cudaGetSymbolAddress((void**)&off, g_off);
    cudaGetSymbolAddress((void**)&fill, g_fill);
    cudaGetSymbolAddress((void**)&csr_src, g_csr_src);
    cudaGetSymbolAddress((void**)&csr_eid, g_csr_eid);

    const int TB = 256;
    const int EB = (ET + TB - 1) / TB;
    const int NB = (N_NODES + TB - 1) / TB;

    // ---- build CSR once (shared by all layers) ----
    detect_dtype_kernel<<<1, 32>>>(ei32);
    zero_int2_kernel<<<NB, TB>>>(deg, fill, N_NODES);
    prep_edges_kernel<<<EB, TB>>>(ei32, src, dst, deg);
    scan_kernel<<<1, 1024>>>(deg, off, N_NODES);
    fill_csr_kernel<<<EB, TB>>>(src, dst, off, fill, csr_src, csr_eid);

    const float* layer_in = x;
    const int Kin[3] = {29, 512, 512};
    const int Hh[3] = {4, 4, 1};
    for (int L = 0; L < 3; L++) {
        int H = Hh[L];
        int NC = H * 128;
        run_gemm(layer_in, W[L], nullptr, xl, N_NODES, NC, Kin[L], 0);
        sd_kernel<<<N_NODES, 32 * H>>>(xl, a_src[L], a_dst[L], sS, sD, H);
        init_softmax_kernel<<<(N_NODES * H + TB - 1) / TB, TB>>>(emax, denom, N_NODES * H);
        edge_max_kernel<<<EB, TB>>>(src, dst, sS, sD, wbuf, emax, H);
        edge_exp_kernel<<<EB, TB>>>(dst, wbuf, emax, denom, H);
        float* outL = (L == 2) ? h2 : hbuf;
        if (H == 4)
            aggregate_kernel<4><<<N_NODES, 128>>>(xl, csr_src, csr_eid, off, wbuf, denom,
                                                  bb[L], bg[L], bbe[L], bm[L], bv[L], outL);
        else
            aggregate_kernel<1><<<N_NODES, 128>>>(xl, csr_src, csr_eid, off, wbuf, denom,
                                                  bb[L], bg[L], bbe[L], bm[L], bv[L], outL);
        layer_in = outL;
    }

    // head
    run_gemm(h2, hw1, hb1, z, N_NODES, 128, 128, 1);
    head2_kernel<<<(N_NODES * 32 + TB - 1) / TB, TB>>>(z, hw2, hb2, out);
}

// round 6
// speedup vs baseline: 1.3802x; 1.3802x over previous
#include <cuda_runtime.h>
#include <math.h>

#define N_NODES 20000
#define N_EDGES 320000
#define ET (N_EDGES + N_NODES)   // edges + self loops = 340000
#define LRELU_SLOPE 0.2f
#define BN_EPS 1e-5f
#define NBLK ((N_NODES + 127) / 128)   // 157

// ---------------- scratch (device globals; no allocation allowed) ----------------
__device__ __align__(16) float g_xl[N_NODES * 512];     // per-layer x@W
__device__ __align__(16) float g_h [N_NODES * 512];     // per-layer output
__device__ __align__(16) float g_h2[N_NODES * 128];     // layer-2 output
__device__ __align__(16) float g_z [N_NODES * 128];     // head hidden
__device__ __align__(16) float g_xpad[N_NODES * 32];    // x padded K 29->32
__device__ __align__(16) float g_w0pad[32 * 512];       // W0 padded rows 29->32
__device__ float g_s[N_NODES * 4], g_d[N_NODES * 4];
__device__ float g_denom[N_NODES * 4];
__device__ float g_alpha[ET * 4];       // per-edge unnormalized alpha, CSR order
__device__ int g_src[ET], g_dst[ET];
__device__ int g_deg[N_NODES], g_off[N_NODES + 1], g_fill[N_NODES];
__device__ int g_csr_src[ET];
__device__ int g_bsum[NBLK], g_bpre[NBLK];
__device__ int g_is64;                  // edge_index dtype flag (1 = int64)

// ---------------- small utility kernels ----------------
__global__ void detect_dtype_kernel(const int* __restrict__ ei32) {
    if (threadIdx.x == 0 && blockIdx.x == 0) {
        int allz = 1;
        #pragma unroll
        for (int j = 0; j < 8; j++)
            if (ei32[2 * j + 1] != 0) allz = 0;
        g_is64 = allz;
    }
}

__global__ void zero_int2_kernel(int* a, int* b, int n) {
    int i = blockIdx.x * blockDim.x + threadIdx.x;
    if (i < n) { a[i] = 0; b[i] = 0; }
}

__global__ void pad_x_kernel(const float* __restrict__ x, float* __restrict__ xpad) {
    int i = blockIdx.x * blockDim.x + threadIdx.x;
    if (i >= N_NODES * 32) return;
    int r = i >> 5, c = i & 31;
    xpad[i] = (c < 29) ? x[r * 29 + c] : 0.f;
}

__global__ void pad_w0_kernel(const float* __restrict__ W0, float* __restrict__ wpad) {
    int i = blockIdx.x * blockDim.x + threadIdx.x;
    if (i >= 32 * 512) return;
    int r = i >> 9, c = i & 511;
    wpad[i] = (r < 29) ? W0[r * 512 + c] : 0.f;
}

__global__ void prep_edges_kernel(const int* __restrict__ ei32,
                                  int* __restrict__ src, int* __restrict__ dst,
                                  int* __restrict__ deg) {
    int i = blockIdx.x * blockDim.x + threadIdx.x;
    if (i >= ET) return;
    int u, v;
    if (i < N_EDGES) {
        if (g_is64) { u = ei32[2 * i]; v = ei32[2 * (N_EDGES + i)]; }
        else        { u = ei32[i];     v = ei32[N_EDGES + i]; }
    } else {
        u = v = i - N_EDGES;
    }
    u = min(max(u, 0), N_NODES - 1);
    v = min(max(v, 0), N_NODES - 1);
    src[i] = u; dst[i] = v;
    atomicAdd(&deg[v], 1);
}

// ---------------- multi-block exclusive scan of degrees ----------------
__global__ void block_sum_kernel(const int* __restrict__ deg, int* __restrict__ bsum) {
    __shared__ int sh[128];
    int t = threadIdx.x, i = blockIdx.x * 128 + t;
    sh[t] = (i < N_NODES) ? deg[i] : 0;
    __syncthreads();
    for (int o = 64; o; o >>= 1) {
        if (t < o) sh[t] += sh[t + o];
        __syncthreads();
    }
    if (t == 0) bsum[blockIdx.x] = sh[0];
}

__global__ void scan_bsum_kernel(const int* __restrict__ bsum, int* __restrict__ bpre,
                                 int* __restrict__ off) {
    __shared__ int sh[256];
    int t = threadIdx.x;
    int val = (t < NBLK) ? bsum[t] : 0;
    sh[t] = val;
    __syncthreads();
    for (int o = 1; o < 256; o <<= 1) {
        int v = (t >= o) ? sh[t - o] : 0;
        __syncthreads();
        sh[t] += v;
        __syncthreads();
    }
    if (t < NBLK) bpre[t] = sh[t] - val;
    if (t == 255) off[N_NODES] = sh[255];
}

__global__ void write_off_kernel(const int* __restrict__ deg, const int* __restrict__ bpre,
                                 int* __restrict__ off) {
    __shared__ int sh[128];
    int t = threadIdx.x, i = blockIdx.x * 128 + t;
    int val = (i < N_NODES) ? deg[i] : 0;
    sh[t] = val;
    __syncthreads();
    for (int o = 1; o < 128; o <<= 1) {
        int v = (t >= o) ? sh[t - o] : 0;
        __syncthreads();
        sh[t] += v;
        __syncthreads();
    }
    if (i < N_NODES) off[i] = bpre[blockIdx.x] + sh[t] - val;
}

__global__ void fill_csr_kernel(const int* __restrict__ src, const int* __restrict__ dst,
                                const int* __restrict__ off, int* __restrict__ fill,
                                int* __restrict__ csr_src) {
    int i = blockIdx.x * blockDim.x + threadIdx.x;
    if (i >= ET) return;
    int v = dst[i];
    int pos = off[v] + atomicAdd(&fill[v], 1);
    csr_src[pos] = src[i];
}

// ---------------- fp32 SGEMM 128x128, TM=TN=8, float4 everywhere ----------------
// Requires: K % 16 == 0, N % 128 == 0.  EPI=1 -> bias + relu.
template <int EPI>
__global__ void __launch_bounds__(256) sgemm128_kernel(
        const float* __restrict__ A, const float* __restrict__ B,
        const float* __restrict__ bias, float* __restrict__ C,
        int M, int N, int K) {
    __shared__ float As[16][128];
    __shared__ float Bs[16][128];
    const int tid = threadIdx.x;
    const int rowBase = blockIdx.y * 128;
    const int colBase = blockIdx.x * 128;
    const int tx = tid & 15;       // 0..15
    const int ty = tid >> 4;       // 0..15
    float acc[8][8] = {};
    for (int k0 = 0; k0 < K; k0 += 16) {
        #pragma unroll
        for (int it = 0; it < 2; it++) {
            int idx = tid + it * 256;            // 0..511
            int r  = idx >> 2;                   // 0..127
            int kq = (idx & 3) << 2;             // 0,4,8,12
            int gr = min(rowBase + r, M - 1);
            const float4 av = *(const float4*)(A + (size_t)gr * K + k0 + kq);
            As[kq + 0][r] = av.x; As[kq + 1][r] = av.y;
            As[kq + 2][r] = av.z; As[kq + 3][r] = av.w;
            int kk = idx >> 5;                   // 0..15
            int nq = (idx & 31) << 2;            // 0..124
            *(float4*)&Bs[kk][nq] =
                *(const float4*)(B + (size_t)(k0 + kk) * N + colBase + nq);
        }
        __syncthreads();
        #pragma unroll
        for (int kk = 0; kk < 16; kk++) {
            float a[8], b[8];
            *(float4*)&a[0] = *(float4*)&As[kk][ty * 8];
            *(float4*)&a[4] = *(float4*)&As[kk][ty * 8 + 4];
            *(float4*)&b[0] = *(float4*)&Bs[kk][tx * 8];
            *(float4*)&b[4] = *(float4*)&Bs[kk][tx * 8 + 4];
            #pragma unroll
            for (int i = 0; i < 8; i++)
                #pragma unroll
                for (int j = 0; j < 8; j++)
                    acc[i][j] += a[i] * b[j];
        }
        __syncthreads();
    }
    #pragma unroll
    for (int i = 0; i < 8; i++) {
        int r = rowBase + ty * 8 + i;
        if (r >= M) continue;
        #pragma unroll
        for (int j = 0; j < 8; j += 4) {
            int c = colBase + tx * 8 + j;
            float4 v = make_float4(acc[i][j], acc[i][j + 1], acc[i][j + 2], acc[i][j + 3]);
            if (EPI == 1) {
                v.x += bias[c + 0]; v.y += bias[c + 1];
                v.z += bias[c + 2]; v.w += bias[c + 3];
                v.x = fmaxf(v.x, 0.f); v.y = fmaxf(v.y, 0.f);
                v.z = fmaxf(v.z, 0.f); v.w = fmaxf(v.w, 0.f);
            }
            *(float4*)(C + (size_t)r * N + c) = v;
        }
    }
}

// ---------------- per-node attention score terms s, d ----------------
__global__ void sd_kernel(const float* __restrict__ xl, const float* __restrict__ a_src,
                          const float* __restrict__ a_dst, float* __restrict__ s,
                          float* __restrict__ d, int H) {
    int n = blockIdx.x;
    int w = threadIdx.x >> 5, l = threadIdx.x & 31;
    if (w >= H) return;
    const float* row = xl + (size_t)n * H * 128 + w * 128;
    float ps = 0.f, pd = 0.f;
    #pragma unroll
    for (int k = 0; k < 4; k++) {
        int c = l + 32 * k;
        float v = row[c];
        ps += v * a_src[w * 128 + c];
        pd += v * a_dst[w * 128 + c];
    }
    #pragma unroll
    for (int o = 16; o; o >>= 1) {
        ps += __shfl_down_sync(0xffffffffu, ps, o);
        pd += __shfl_down_sync(0xffffffffu, pd, o);
    }
    if (l == 0) { s[n * H + w] = ps; d[n * H + w] = pd; }
}

// ---------------- warp-per-node softmax over incoming edges (CSR order) ----------
template <int H>
__global__ void attention_kernel(const int* __restrict__ csr_src, const int* __restrict__ off,
                                 const float* __restrict__ s, const float* __restrict__ d,
                                 float* __restrict__ alpha, float* __restrict__ denom) {
    int n = (blockIdx.x * blockDim.x + threadIdx.x) >> 5;
    int lane = threadIdx.x & 31;
    if (n >= N_NODES) return;
    int s0 = off[n], s1 = off[n + 1];
    float dh[H], m[H], sum[H];
    #pragma unroll
    for (int h = 0; h < H; h++) { dh[h] = d[n * H + h]; m[h] = -3.0e38f; sum[h] = 0.f; }
    // pass 1: raw leaky-relu scores + running max
    for (int p = s0 + lane; p < s1; p += 32) {
        int u = csr_src[p];
        #pragma unroll
        for (int h = 0; h < H; h++) {
            float e = s[u * H + h] + dh[h];
            e = e > 0.f ? e : LRELU_SLOPE * e;
            alpha[p * H + h] = e;
            m[h] = fmaxf(m[h], e);
        }
    }
    #pragma unroll
    for (int h = 0; h < H; h++)
        #pragma unroll
        for (int o = 16; o; o >>= 1)
            m[h] = fmaxf(m[h], __shfl_xor_sync(0xffffffffu, m[h], o));
    // pass 2: exp + sum (each lane re-reads exactly what it wrote)
    for (int p = s0 + lane; p < s1; p += 32) {
        #pragma unroll
        for (int h = 0; h < H; h++) {
            float ee = expf(alpha[p * H + h] - m[h]);
            alpha[p * H + h] = ee;
            sum[h] += ee;
        }
    }
    #pragma unroll
    for (int h = 0; h < H; h++)
        #pragma unroll
        for (int o = 16; o; o >>= 1)
            sum[h] += __shfl_xor_sync(0xffffffffu, sum[h], o);
    if (lane == 0)
        #pragma unroll
        for (int h = 0; h < H; h++) denom[n * H + h] = sum[h];
}

// ---------------- per-node weighted aggregation + bias + BN + ELU ----------------
template <int H>
__global__ void aggregate_kernel(const float* __restrict__ xl, const int* __restrict__ csr_src,
                                 const int* __restrict__ off,
                                 const float* __restrict__ alpha, const float* __restrict__ denom,
                                 const float* __restrict__ bias, const float* __restrict__ bg,
                                 const float* __restrict__ bbe, const float* __restrict__ bm,
                                 const float* __restrict__ bv, float* __restrict__ out) {
    int n = blockIdx.x;
    int t = threadIdx.x;  // 128 threads
    float acc[H];
    #pragma unroll
    for (int h = 0; h < H; h++) acc[h] = 0.f;
    int s0 = off[n], s1 = off[n + 1];
    __shared__ int sh_src[32];
    __shared__ float sh_w[32][H];
    for (int base = s0; base < s1; base += 32) {
        int cnt = min(32, s1 - base);
        if (t < cnt) sh_src[t] = csr_src[base + t];
        if (t < cnt * H) {
            int j = t / H, h = t % H;
            sh_w[j][h] = alpha[(base + j) * H + h];
        }
        __syncthreads();
        for (int j = 0; j < cnt; j++) {
            const float* row = xl + (size_t)sh_src[j] * (H * 128);
            #pragma unroll
            for (int h = 0; h < H; h++) acc[h] += sh_w[j][h] * row[h * 128 + t];
        }
        __syncthreads();
    }
    #pragma unroll
    for (int h = 0; h < H; h++) {
        int c = h * 128 + t;
        float val = acc[h] / (denom[n * H + h] + 1e-16f) + bias[c];
        float sc = bg[c] * rsqrtf(bv[c] + BN_EPS);
        val = (val - bm[c]) * sc + bbe[c];
        out[(size_t)n * (H * 128) + c] = val > 0.f ? val : expm1f(val);
    }
}

// ---------------- head layer 2: [N,128] @ [128,9] + bias ----------------
__global__ void head2_kernel(const float* __restrict__ z, const float* __restrict__ hw2,
                             const float* __restrict__ hb2, float* __restrict__ out) {
    int warp = (blockIdx.x * blockDim.x + threadIdx.x) >> 5;
    int lane = threadIdx.x & 31;
    if (warp >= N_NODES) return;
    const float* row = z + (size_t)warp * 128;
    float zv[4];
    #pragma unroll
    for (int i = 0; i < 4; i++) zv[i] = row[lane + 32 * i];
    for (int j = 0; j < 9; j++) {
        float p = 0.f;
        #pragma unroll
        for (int i = 0; i < 4; i++) p += zv[i] * hw2[(lane + 32 * i) * 9 + j];
        #pragma unroll
        for (int o = 16; o; o >>= 1) p += __shfl_down_sync(0xffffffffu, p, o);
        if (lane == 0) out[warp * 9 + j] = p + hb2[j];
    }
}

// ---------------- driver ----------------
static void run_gemm(const float* A, const float* B, const float* bias, float* C,
                     int M, int N, int K, int epi) {
    dim3 grid(N / 128, (M + 127) / 128);
    if (epi)
        sgemm128_kernel<1><<<grid, 256>>>(A, B, bias, C, M, N, K);
    else
        sgemm128_kernel<0><<<grid, 256>>>(A, B, bias, C, M, N, K);
}

extern "C" void kernel_launch(void* const* d_in, const int* in_sizes, int n_in,
                              void* d_out, int out_size) {
    const float* x = (const float*)d_in[0];
    const int* ei32 = (const int*)d_in[1];   // int32 OR int64 (detected on device)

    bool sig_order = (in_sizes[6] > 100000);
    const float *W[3], *a_src[3], *a_dst[3], *bb[3], *bg[3], *bbe[3], *bm[3], *bv[3];
    if (sig_order) {
        const int wi[3] = {2, 6, 10};
        const int gi[3] = {14, 18, 22};
        for (int i = 0; i < 3; i++) {
            W[i]     = (const float*)d_in[wi[i] + 0];
            a_src[i] = (const float*)d_in[wi[i] + 1];
            a_dst[i] = (const float*)d_in[wi[i] + 2];
            bb[i]    = (const float*)d_in[wi[i] + 3];
            bg[i]    = (const float*)d_in[gi[i] + 0];
            bbe[i]   = (const float*)d_in[gi[i] + 1];
            bm[i]    = (const float*)d_in[gi[i] + 2];
            bv[i]    = (const float*)d_in[gi[i] + 3];
        }
    } else {
        const int base[3] = {2, 10, 18};
        for (int i = 0; i < 3; i++) {
            W[i]     = (const float*)d_in[base[i] + 0];
            a_src[i] = (const float*)d_in[base[i] + 1];
            a_dst[i] = (const float*)d_in[base[i] + 2];
            bb[i]    = (const float*)d_in[base[i] + 3];
            bg[i]    = (const float*)d_in[base[i] + 4];
            bbe[i]   = (const float*)d_in[base[i] + 5];
            bm[i]    = (const float*)d_in[base[i] + 6];
            bv[i]    = (const float*)d_in[base[i] + 7];
        }
    }
    const float* hw1 = (const float*)d_in[26];
    const float* hb1 = (const float*)d_in[27];
    const float* hw2 = (const float*)d_in[28];
    const float* hb2 = (const float*)d_in[29];
    float* out = (float*)d_out;

    // scratch addresses
    float *xl, *hbuf, *h2, *z, *xpad, *w0pad, *sS, *sD, *denom, *alpha;
    int *src, *dst, *deg, *off, *fill, *csr_src, *bsum, *bpre;
    cudaGetSymbolAddress((void**)&xl, g_xl);
    cudaGetSymbolAddress((void**)&hbuf, g_h);
    cudaGetSymbolAddress((void**)&h2, g_h2);
    cudaGetSymbolAddress((void**)&z, g_z);
    cudaGetSymbolAddress((void**)&xpad, g_xpad);
    cudaGetSymbolAddress((void**)&w0pad, g_w0pad);
    cudaGetSymbolAddress((void**)&sS, g_s);
    cudaGetSymbolAddress((void**)&sD, g_d);
    cudaGetSymbolAddress((void**)&denom, g_denom);
    cudaGetSymbolAddress((void**)&alpha, g_alpha);
    cudaGetSymbolAddress((void**)&src, g_src);
    cudaGetSymbolAddress((void**)&dst, g_dst);
    cudaGetSymbolAddress((void**)&deg, g_deg);
    cudaGetSymbolAddress((void**)&off, g_off);
    cudaGetSymbolAddress((void**)&fill, g_fill);
    cudaGetSymbolAddress((void**)&csr_src, g_csr_src);
    cudaGetSymbolAddress((void**)&bsum, g_bsum);
    cudaGetSymbolAddress((void**)&bpre, g_bpre);

    const int TB = 256;
    const int EB = (ET + TB - 1) / TB;
    const int NB = (N_NODES + TB - 1) / TB;

    // ---- build CSR (shared by all layers) + pad inputs for vector GEMM ----
    detect_dtype_kernel<<<1, 32>>>(ei32);
    zero_int2_kernel<<<NB, TB>>>(deg, fill, N_NODES);
    pad_x_kernel<<<(N_NODES * 32 + TB - 1) / TB, TB>>>(x, xpad);
    pad_w0_kernel<<<(32 * 512 + TB - 1) / TB, TB>>>(W[0], w0pad);
    prep_edges_kernel<<<EB, TB>>>(ei32, src, dst, deg);
    block_sum_kernel<<<NBLK, 128>>>(deg, bsum);
    scan_bsum_kernel<<<1, 256>>>(bsum, bpre, off);
    write_off_kernel<<<NBLK, 128>>>(deg, bpre, off);
    fill_csr_kernel<<<EB, TB>>>(src, dst, off, fill, csr_src);

    const float* layer_in = xpad;
    const float* layer_W;
    const int Kin[3] = {32, 512, 512};
    const int Hh[3]  = {4, 4, 1};
    for (int L = 0; L < 3; L++) {
        int H = Hh[L];
        int NC = H * 128;
        layer_W = (L == 0) ? w0pad : W[L];
        run_gemm(layer_in, layer_W, nullptr, xl, N_NODES, NC, Kin[L], 0);
        sd_kernel<<<N_NODES, 32 * H>>>(xl, a_src[L], a_dst[L], sS, sD, H);
        if (H == 4) {
            attention_kernel<4><<<(N_NODES * 32 + 127) / 128, 128>>>(csr_src, off, sS, sD, alpha, denom);
            aggregate_kernel<4><<<N_NODES, 128>>>(xl, csr_src, off, alpha, denom,
                                                  bb[L], bg[L], bbe[L], bm[L], bv[L], hbuf);
            layer_in = hbuf;
        } else {
            attention_kernel<1><<<(N_NODES * 32 + 127) / 128, 128>>>(csr_src, off, sS, sD, alpha, denom);
            aggregate_kernel<1><<<N_NODES, 128>>>(xl, csr_src, off, alpha, denom,
                                                  bb[L], bg[L], bbe[L], bm[L], bv[L], h2);
            layer_in = h2;
        }
    }

    // head
    run_gemm(h2, hw1, hb1, z, N_NODES, 128, 128, 1);
    head2_kernel<<<(N_NODES * 32 + TB - 1) / TB, TB>>>(z, hw2, hb2, out);
}

// round 7
// speedup vs baseline: 1.6103x; 1.1667x over previous
#include <cuda_runtime.h>
#include <math.h>
#include <stdint.h>

#define N_NODES 20000
#define N_EDGES 320000
#define ET (N_EDGES + N_NODES)   // edges + self loops = 340000
#define LRELU_SLOPE 0.2f
#define BN_EPS 1e-5f
#define NBLK ((N_NODES + 127) / 128)   // 157

// ---------------- scratch (device globals; no allocation allowed) ----------------
__device__ __align__(16) float g_xl[N_NODES * 512];     // per-layer x@W
__device__ __align__(16) float g_h [N_NODES * 512];     // per-layer output
__device__ __align__(16) float g_h2[N_NODES * 128];     // layer-2 output
__device__ __align__(16) float g_z [N_NODES * 128];     // head hidden
__device__ __align__(16) float g_xpad[N_NODES * 32];    // x padded K 29->32
__device__ __align__(16) float g_w0pad[32 * 512];       // W0 padded rows 29->32
__device__ float g_s[N_NODES * 4], g_d[N_NODES * 4];
__device__ float g_denom[N_NODES * 4];
__device__ float g_alpha[ET * 4];       // per-edge unnormalized alpha, CSR order
__device__ int g_src[ET], g_dst[ET];
__device__ int g_deg[N_NODES], g_off[N_NODES + 1], g_fill[N_NODES];
__device__ int g_csr_src[ET];
__device__ int g_bsum[NBLK], g_bpre[NBLK];
__device__ int g_is64;                  // edge_index dtype flag (1 = int64)

// ---------------- small utility kernels ----------------
__global__ void detect_dtype_kernel(const int* __restrict__ ei32) {
    if (threadIdx.x == 0 && blockIdx.x == 0) {
        int allz = 1;
        #pragma unroll
        for (int j = 0; j < 8; j++)
            if (ei32[2 * j + 1] != 0) allz = 0;
        g_is64 = allz;
    }
}

__global__ void zero_int2_kernel(int* a, int* b, int n) {
    int i = blockIdx.x * blockDim.x + threadIdx.x;
    if (i < n) { a[i] = 0; b[i] = 0; }
}

__global__ void pad_x_kernel(const float* __restrict__ x, float* __restrict__ xpad) {
    int i = blockIdx.x * blockDim.x + threadIdx.x;
    if (i >= N_NODES * 32) return;
    int r = i >> 5, c = i & 31;
    xpad[i] = (c < 29) ? x[r * 29 + c] : 0.f;
}

__global__ void pad_w0_kernel(const float* __restrict__ W0, float* __restrict__ wpad) {
    int i = blockIdx.x * blockDim.x + threadIdx.x;
    if (i >= 32 * 512) return;
    int r = i >> 9, c = i & 511;
    wpad[i] = (r < 29) ? W0[r * 512 + c] : 0.f;
}

__global__ void prep_edges_kernel(const int* __restrict__ ei32,
                                  int* __restrict__ src, int* __restrict__ dst,
                                  int* __restrict__ deg) {
    int i = blockIdx.x * blockDim.x + threadIdx.x;
    if (i >= ET) return;
    int u, v;
    if (i < N_EDGES) {
        if (g_is64) { u = ei32[2 * i]; v = ei32[2 * (N_EDGES + i)]; }
        else        { u = ei32[i];     v = ei32[N_EDGES + i]; }
    } else {
        u = v = i - N_EDGES;
    }
    u = min(max(u, 0), N_NODES - 1);
    v = min(max(v, 0), N_NODES - 1);
    src[i] = u; dst[i] = v;
    atomicAdd(&deg[v], 1);
}

// ---------------- multi-block exclusive scan of degrees ----------------
__global__ void block_sum_kernel(const int* __restrict__ deg, int* __restrict__ bsum) {
    __shared__ int sh[128];
    int t = threadIdx.x, i = blockIdx.x * 128 + t;
    sh[t] = (i < N_NODES) ? deg[i] : 0;
    __syncthreads();
    for (int o = 64; o; o >>= 1) {
        if (t < o) sh[t] += sh[t + o];
        __syncthreads();
    }
    if (t == 0) bsum[blockIdx.x] = sh[0];
}

__global__ void scan_bsum_kernel(const int* __restrict__ bsum, int* __restrict__ bpre,
                                 int* __restrict__ off) {
    __shared__ int sh[256];
    int t = threadIdx.x;
    int val = (t < NBLK) ? bsum[t] : 0;
    sh[t] = val;
    __syncthreads();
    for (int o = 1; o < 256; o <<= 1) {
        int v = (t >= o) ? sh[t - o] : 0;
        __syncthreads();
        sh[t] += v;
        __syncthreads();
    }
    if (t < NBLK) bpre[t] = sh[t] - val;
    if (t == 255) off[N_NODES] = sh[255];
}

__global__ void write_off_kernel(const int* __restrict__ deg, const int* __restrict__ bpre,
                                 int* __restrict__ off) {
    __shared__ int sh[128];
    int t = threadIdx.x, i = blockIdx.x * 128 + t;
    int val = (i < N_NODES) ? deg[i] : 0;
    sh[t] = val;
    __syncthreads();
    for (int o = 1; o < 128; o <<= 1) {
        int v = (t >= o) ? sh[t - o] : 0;
        __syncthreads();
        sh[t] += v;
        __syncthreads();
    }
    if (i < N_NODES) off[i] = bpre[blockIdx.x] + sh[t] - val;
}

__global__ void fill_csr_kernel(const int* __restrict__ src, const int* __restrict__ dst,
                                const int* __restrict__ off, int* __restrict__ fill,
                                int* __restrict__ csr_src) {
    int i = blockIdx.x * blockDim.x + threadIdx.x;
    if (i >= ET) return;
    int v = dst[i];
    int pos = off[v] + atomicAdd(&fill[v], 1);
    csr_src[pos] = src[i];
}

// ---------------- 3xTF32 tensor-core GEMM (m16n8k8) ----------------
// C[M,N] = A[M,K] @ B[K,N], fp32 in/out, ~fp32 accuracy via hi/lo tf32 split.
// Requires K % 32 == 0, N % 128 == 0. EPI=1 -> bias + relu.
__device__ __forceinline__ void split_tf32(float x, uint32_t& hi, uint32_t& lo) {
    asm("cvt.rna.tf32.f32 %0, %1;" : "=r"(hi) : "f"(x));
    float r = x - __uint_as_float(hi);
    asm("cvt.rna.tf32.f32 %0, %1;" : "=r"(lo) : "f"(r));
}

#define MMA8(d, a, b)                                                          \
    asm volatile(                                                              \
        "mma.sync.aligned.m16n8k8.row.col.f32.tf32.tf32.f32 "                  \
        "{%0,%1,%2,%3},{%4,%5,%6,%7},{%8,%9},{%0,%1,%2,%3};"                   \
        : "+f"(d[0]), "+f"(d[1]), "+f"(d[2]), "+f"(d[3])                       \
        : "r"(a[0]), "r"(a[1]), "r"(a[2]), "r"(a[3]), "r"(b[0]), "r"(b[1]))

template <int EPI>
__global__ void __launch_bounds__(256) tf32gemm_kernel(
        const float* __restrict__ A, const float* __restrict__ B,
        const float* __restrict__ bias, float* __restrict__ C,
        int M, int N, int K) {
    __shared__ float As[128][36];   // stride 36: (4g+tg)%32 unique -> conflict-free frag reads
    __shared__ float Bs[32][136];   // stride 136: (8tg+g)%32 unique -> conflict-free
    const int tid = threadIdx.x;
    const int wid = tid >> 5, lane = tid & 31;
    const int g = lane >> 2, tg = lane & 3;
    const int warp_m = (wid & 1) * 64;    // 2 warps along M
    const int warp_n = (wid >> 1) * 32;   // 4 warps along N
    const int rowBase = blockIdx.y * 128;
    const int colBase = blockIdx.x * 128;

    float acc[4][4][4];
    #pragma unroll
    for (int i = 0; i < 4; i++)
        #pragma unroll
        for (int j = 0; j < 4; j++)
            #pragma unroll
            for (int q = 0; q < 4; q++) acc[i][j][q] = 0.f;

    for (int k0 = 0; k0 < K; k0 += 32) {
        // load A tile 128x32 (float4)
        #pragma unroll
        for (int it = 0; it < 4; it++) {
            int idx = tid + it * 256;        // 0..1023
            int r = idx >> 3;                // 0..127
            int c = (idx & 7) << 2;          // 0..28
            int gr = rowBase + r;
            if (gr >= M) gr = M - 1;
            float4 v = *(const float4*)(A + (size_t)gr * K + k0 + c);
            As[r][c] = v.x; As[r][c + 1] = v.y; As[r][c + 2] = v.z; As[r][c + 3] = v.w;
        }
        // load B tile 32x128 (float4)
        #pragma unroll
        for (int it = 0; it < 4; it++) {
            int idx = tid + it * 256;
            int r = idx >> 5;                // 0..31
            int c = (idx & 31) << 2;         // 0..124
            *(float4*)&Bs[r][c] = *(const float4*)(B + (size_t)(k0 + r) * N + colBase + c);
        }
        __syncthreads();

        #pragma unroll
        for (int ks = 0; ks < 4; ks++) {
            const int kb = ks * 8;
            uint32_t ahi[4][4], alo[4][4];
            #pragma unroll
            for (int mf = 0; mf < 4; mf++) {
                int mr = warp_m + mf * 16;
                split_tf32(As[mr + g][kb + tg],          ahi[mf][0], alo[mf][0]);
                split_tf32(As[mr + g + 8][kb + tg],      ahi[mf][1], alo[mf][1]);
                split_tf32(As[mr + g][kb + tg + 4],      ahi[mf][2], alo[mf][2]);
                split_tf32(As[mr + g + 8][kb + tg + 4],  ahi[mf][3], alo[mf][3]);
            }
            uint32_t bhi[4][2], blo[4][2];
            #pragma unroll
            for (int nf = 0; nf < 4; nf++) {
                int nc = warp_n + nf * 8 + g;
                split_tf32(Bs[kb + tg][nc],     bhi[nf][0], blo[nf][0]);
                split_tf32(Bs[kb + tg + 4][nc], bhi[nf][1], blo[nf][1]);
            }
            #pragma unroll
            for (int mf = 0; mf < 4; mf++)
                #pragma unroll
                for (int nf = 0; nf < 4; nf++) {
                    MMA8(acc[mf][nf], ahi[mf], blo[nf]);
                    MMA8(acc[mf][nf], alo[mf], bhi[nf]);
                    MMA8(acc[mf][nf], ahi[mf], bhi[nf]);
                }
        }
        __syncthreads();
    }

    // epilogue
    #pragma unroll
    for (int mf = 0; mf < 4; mf++) {
        #pragma unroll
        for (int nf = 0; nf < 4; nf++) {
            int c = colBase + warp_n + nf * 8 + 2 * tg;
            int r0 = rowBase + warp_m + mf * 16 + g;
            int r1 = r0 + 8;
            float2 v0 = make_float2(acc[mf][nf][0], acc[mf][nf][1]);
            float2 v1 = make_float2(acc[mf][nf][2], acc[mf][nf][3]);
            if (EPI == 1) {
                float b0 = bias[c], b1 = bias[c + 1];
                v0.x = fmaxf(v0.x + b0, 0.f); v0.y = fmaxf(v0.y + b1, 0.f);
                v1.x = fmaxf(v1.x + b0, 0.f); v1.y = fmaxf(v1.y + b1, 0.f);
            }
            if (r0 < M) *(float2*)(C + (size_t)r0 * N + c) = v0;
            if (r1 < M) *(float2*)(C + (size_t)r1 * N + c) = v1;
        }
    }
}

// ---------------- per-node attention score terms s, d ----------------
__global__ void sd_kernel(const float* __restrict__ xl, const float* __restrict__ a_src,
                          const float* __restrict__ a_dst, float* __restrict__ s,
                          float* __restrict__ d, int H) {
    int n = blockIdx.x;
    int w = threadIdx.x >> 5, l = threadIdx.x & 31;
    if (w >= H) return;
    const float* row = xl + (size_t)n * H * 128 + w * 128;
    float ps = 0.f, pd = 0.f;
    #pragma unroll
    for (int k = 0; k < 4; k++) {
        int c = l + 32 * k;
        float v = row[c];
        ps += v * a_src[w * 128 + c];
        pd += v * a_dst[w * 128 + c];
    }
    #pragma unroll
    for (int o = 16; o; o >>= 1) {
        ps += __shfl_down_sync(0xffffffffu, ps, o);
        pd += __shfl_down_sync(0xffffffffu, pd, o);
    }
    if (l == 0) { s[n * H + w] = ps; d[n * H + w] = pd; }
}

// ---------------- warp-per-node softmax over incoming edges (CSR order) ----------
template <int H>
__global__ void attention_kernel(const int* __restrict__ csr_src, const int* __restrict__ off,
                                 const float* __restrict__ s, const float* __restrict__ d,
                                 float* __restrict__ alpha, float* __restrict__ denom) {
    int n = (blockIdx.x * blockDim.x + threadIdx.x) >> 5;
    int lane = threadIdx.x & 31;
    if (n >= N_NODES) return;
    int s0 = off[n], s1 = off[n + 1];
    float dh[H], m[H], sum[H];
    #pragma unroll
    for (int h = 0; h < H; h++) { dh[h] = d[n * H + h]; m[h] = -3.0e38f; sum[h] = 0.f; }
    for (int p = s0 + lane; p < s1; p += 32) {
        int u = csr_src[p];
        #pragma unroll
        for (int h = 0; h < H; h++) {
            float e = s[u * H + h] + dh[h];
            e = e > 0.f ? e : LRELU_SLOPE * e;
            alpha[p * H + h] = e;
            m[h] = fmaxf(m[h], e);
        }
    }
    #pragma unroll
    for (int h = 0; h < H; h++)
        #pragma unroll
        for (int o = 16; o; o >>= 1)
            m[h] = fmaxf(m[h], __shfl_xor_sync(0xffffffffu, m[h], o));
    for (int p = s0 + lane; p < s1; p += 32) {
        #pragma unroll
        for (int h = 0; h < H; h++) {
            float ee = expf(alpha[p * H + h] - m[h]);
            alpha[p * H + h] = ee;
            sum[h] += ee;
        }
    }
    #pragma unroll
    for (int h = 0; h < H; h++)
        #pragma unroll
        for (int o = 16; o; o >>= 1)
            sum[h] += __shfl_xor_sync(0xffffffffu, sum[h], o);
    if (lane == 0)
        #pragma unroll
        for (int h = 0; h < H; h++) denom[n * H + h] = sum[h];
}

// ---------------- per-node weighted aggregation + bias + BN + ELU ----------------
template <int H>
__global__ void aggregate_kernel(const float* __restrict__ xl, const int* __restrict__ csr_src,
                                 const int* __restrict__ off,
                                 const float* __restrict__ alpha, const float* __restrict__ denom,
                                 const float* __restrict__ bias, const float* __restrict__ bg,
                                 const float* __restrict__ bbe, const float* __restrict__ bm,
                                 const float* __restrict__ bv, float* __restrict__ out) {
    int n = blockIdx.x;
    int t = threadIdx.x;  // 128 threads
    float acc[H];
    #pragma unroll
    for (int h = 0; h < H; h++) acc[h] = 0.f;
    int s0 = off[n], s1 = off[n + 1];
    __shared__ int sh_src[32];
    __shared__ float sh_w[32][H];
    for (int base = s0; base < s1; base += 32) {
        int cnt = min(32, s1 - base);
        if (t < cnt) sh_src[t] = csr_src[base + t];
        if (t < cnt * H) {
            int j = t / H, h = t % H;
            sh_w[j][h] = alpha[(base + j) * H + h];
        }
        __syncthreads();
        for (int j = 0; j < cnt; j++) {
            const float* row = xl + (size_t)sh_src[j] * (H * 128);
            #pragma unroll
            for (int h = 0; h < H; h++) acc[h] += sh_w[j][h] * row[h * 128 + t];
        }
        __syncthreads();
    }
    #pragma unroll
    for (int h = 0; h < H; h++) {
        int c = h * 128 + t;
        float val = acc[h] / (denom[n * H + h] + 1e-16f) + bias[c];
        float sc = bg[c] * rsqrtf(bv[c] + BN_EPS);
        val = (val - bm[c]) * sc + bbe[c];
        out[(size_t)n * (H * 128) + c] = val > 0.f ? val : expm1f(val);
    }
}

// ---------------- head layer 2: [N,128] @ [128,9] + bias ----------------
__global__ void head2_kernel(const float* __restrict__ z, const float* __restrict__ hw2,
                             const float* __restrict__ hb2, float* __restrict__ out) {
    int warp = (blockIdx.x * blockDim.x + threadIdx.x) >> 5;
    int lane = threadIdx.x & 31;
    if (warp >= N_NODES) return;
    const float* row = z + (size_t)warp * 128;
    float zv[4];
    #pragma unroll
    for (int i = 0; i < 4; i++) zv[i] = row[lane + 32 * i];
    for (int j = 0; j < 9; j++) {
        float p = 0.f;
        #pragma unroll
        for (int i = 0; i < 4; i++) p += zv[i] * hw2[(lane + 32 * i) * 9 + j];
        #pragma unroll
        for (int o = 16; o; o >>= 1) p += __shfl_down_sync(0xffffffffu, p, o);
        if (lane == 0) out[warp * 9 + j] = p + hb2[j];
    }
}

// ---------------- driver ----------------
static void run_gemm(const float* A, const float* B, const float* bias, float* C,
                     int M, int N, int K, int epi) {
    dim3 grid(N / 128, (M + 127) / 128);
    if (epi)
        tf32gemm_kernel<1><<<grid, 256>>>(A, B, bias, C, M, N, K);
    else
        tf32gemm_kernel<0><<<grid, 256>>>(A, B, bias, C, M, N, K);
}

extern "C" void kernel_launch(void* const* d_in, const int* in_sizes, int n_in,
                              void* d_out, int out_size) {
    const float* x = (const float*)d_in[0];
    const int* ei32 = (const int*)d_in[1];   // int32 OR int64 (detected on device)

    bool sig_order = (in_sizes[6] > 100000);
    const float *W[3], *a_src[3], *a_dst[3], *bb[3], *bg[3], *bbe[3], *bm[3], *bv[3];
    if (sig_order) {
        const int wi[3] = {2, 6, 10};
        const int gi[3] = {14, 18, 22};
        for (int i = 0; i < 3; i++) {
            W[i]     = (const float*)d_in[wi[i] + 0];
            a_src[i] = (const float*)d_in[wi[i] + 1];
            a_dst[i] = (const float*)d_in[wi[i] + 2];
            bb[i]    = (const float*)d_in[wi[i] + 3];
            bg[i]    = (const float*)d_in[gi[i] + 0];
            bbe[i]   = (const float*)d_in[gi[i] + 1];
            bm[i]    = (const float*)d_in[gi[i] + 2];
            bv[i]    = (const float*)d_in[gi[i] + 3];
        }
    } else {
        const int base[3] = {2, 10, 18};
        for (int i = 0; i < 3; i++) {
            W[i]     = (const float*)d_in[base[i] + 0];
            a_src[i] = (const float*)d_in[base[i] + 1];
            a_dst[i] = (const float*)d_in[base[i] + 2];
            bb[i]    = (const float*)d_in[base[i] + 3];
            bg[i]    = (const float*)d_in[base[i] + 4];
            bbe[i]   = (const float*)d_in[base[i] + 5];
            bm[i]    = (const float*)d_in[base[i] + 6];
            bv[i]    = (const float*)d_in[base[i] + 7];
        }
    }
    const float* hw1 = (const float*)d_in[26];
    const float* hb1 = (const float*)d_in[27];
    const float* hw2 = (const float*)d_in[28];
    const float* hb2 = (const float*)d_in[29];
    float* out = (float*)d_out;

    // scratch addresses
    float *xl, *hbuf, *h2, *z, *xpad, *w0pad, *sS, *sD, *denom, *alpha;
    int *src, *dst, *deg, *off, *fill, *csr_src, *bsum, *bpre;
    cudaGetSymbolAddress((void**)&xl, g_xl);
    cudaGetSymbolAddress((void**)&hbuf, g_h);
    cudaGetSymbolAddress((void**)&h2, g_h2);
    cudaGetSymbolAddress((void**)&z, g_z);
    cudaGetSymbolAddress((void**)&xpad, g_xpad);
    cudaGetSymbolAddress((void**)&w0pad, g_w0pad);
    cudaGetSymbolAddress((void**)&sS, g_s);
    cudaGetSymbolAddress((void**)&sD, g_d);
    cudaGetSymbolAddress((void**)&denom, g_denom);
    cudaGetSymbolAddress((void**)&alpha, g_alpha);
    cudaGetSymbolAddress((void**)&src, g_src);
    cudaGetSymbolAddress((void**)&dst, g_dst);
    cudaGetSymbolAddress((void**)&deg, g_deg);
    cudaGetSymbolAddress((void**)&off, g_off);
    cudaGetSymbolAddress((void**)&fill, g_fill);
    cudaGetSymbolAddress((void**)&csr_src, g_csr_src);
    cudaGetSymbolAddress((void**)&bsum, g_bsum);
    cudaGetSymbolAddress((void**)&bpre, g_bpre);

    const int TB = 256;
    const int EB = (ET + TB - 1) / TB;
    const int NB = (N_NODES + TB - 1) / TB;

    // ---- build CSR (shared by all layers) + pad inputs for vector GEMM ----
    detect_dtype_kernel<<<1, 32>>>(ei32);
    zero_int2_kernel<<<NB, TB>>>(deg, fill, N_NODES);
    pad_x_kernel<<<(N_NODES * 32 + TB - 1) / TB, TB>>>(x, xpad);
    pad_w0_kernel<<<(32 * 512 + TB - 1) / TB, TB>>>(W[0], w0pad);
    prep_edges_kernel<<<EB, TB>>>(ei32, src, dst, deg);
    block_sum_kernel<<<NBLK, 128>>>(deg, bsum);
    scan_bsum_kernel<<<1, 256>>>(bsum, bpre, off);
    write_off_kernel<<<NBLK, 128>>>(deg, bpre, off);
    fill_csr_kernel<<<EB, TB>>>(src, dst, off, fill, csr_src);

    const float* layer_in = xpad;
    const float* layer_W;
    const int Kin[3] = {32, 512, 512};
    const int Hh[3]  = {4, 4, 1};
    for (int L = 0; L < 3; L++) {
        int H = Hh[L];
        int NC = H * 128;
        layer_W = (L == 0) ? w0pad : W[L];
        run_gemm(layer_in, layer_W, nullptr, xl, N_NODES, NC, Kin[L], 0);
        sd_kernel<<<N_NODES, 32 * H>>>(xl, a_src[L], a_dst[L], sS, sD, H);
        if (H == 4) {
            attention_kernel<4><<<(N_NODES * 32 + 127) / 128, 128>>>(csr_src, off, sS, sD, alpha, denom);
            aggregate_kernel<4><<<N_NODES, 128>>>(xl, csr_src, off, alpha, denom,
                                                  bb[L], bg[L], bbe[L], bm[L], bv[L], hbuf);
            layer_in = hbuf;
        } else {
            attention_kernel<1><<<(N_NODES * 32 + 127) / 128, 128>>>(csr_src, off, sS, sD, alpha, denom);
            aggregate_kernel<1><<<N_NODES, 128>>>(xl, csr_src, off, alpha, denom,
                                                  bb[L], bg[L], bbe[L], bm[L], bv[L], h2);
            layer_in = h2;
        }
    }

    // head
    run_gemm(h2, hw1, hb1, z, N_NODES, 128, 128, 1);
    head2_kernel<<<(N_NODES * 32 + TB - 1) / TB, TB>>>(z, hw2, hb2, out);
}